// round 11
// baseline (speedup 1.0000x reference)
#include <cuda_runtime.h>
#include <cuda_bf16.h>
#include <cstdint>

// ---------------------------------------------------------------------------
// out[n] = (segment_sum(pred_prob[src], dst)[n] - 1)^2 * special_cost[n]
// N = 1,000,000 nodes, E = 16,000,000 edges.
//
// v11: 2-launch pipeline (scatter -> apply+reset) on zero-initialized
// __device__ scratch.
// Scatter (FROZEN at measured-best): 2 edges/thread, 256 threads, __ldg
// gather, atomicAdd -> RED. Floor ~122.5us (L1tex/LSU path: ~1 cyc/edge
// gather wavefront + ~1.29 cyc/edge spread-RED per SM; axis swept
// 8->135.2, 4->129.3, 2->129.2).
// Apply: 2 elems/thread (float2), 2x CTAs vs v9 -- apply is DRAM-LATENCY
// bound (L2 evicted by scatter's 128MB index stream; issue=8.9%), so more
// concurrent warps -> more outstanding misses. (8/thread lowered occ and
// regressed; going the other direction.)
// ---------------------------------------------------------------------------

#define MAX_NODES 1000000
__device__ float g_accum[MAX_NODES];   // static zero-init

__global__ __launch_bounds__(256) void scatter_accum_kernel(
        const float* __restrict__ pred_prob,
        const int*   __restrict__ src,
        const int*   __restrict__ dst,
        int num_edges) {
    int i = blockIdx.x * blockDim.x + threadIdx.x;
    int base = i * 2;
    if (base + 1 < num_edges) {
        int2 s2 = *reinterpret_cast<const int2*>(src + base);
        int2 d2 = *reinterpret_cast<const int2*>(dst + base);
        float m0 = __ldg(pred_prob + s2.x);
        float m1 = __ldg(pred_prob + s2.y);
        atomicAdd(g_accum + d2.x, m0);   // return unused -> RED
        atomicAdd(g_accum + d2.y, m1);
    } else if (base < num_edges) {
        atomicAdd(g_accum + dst[base], __ldg(pred_prob + src[base]));
    }
}

// Reads accumulated sums, computes (a-1)^2 * cost into out, and resets the
// accumulator to zero so the next (graph-replayed) call starts clean.
// 2 elems/thread: maximize concurrent warps for DRAM-latency hiding.
__global__ __launch_bounds__(256) void apply_reset_kernel(
        const float* __restrict__ special_cost,
        float*       __restrict__ out,
        int n) {
    int i = blockIdx.x * blockDim.x + threadIdx.x;
    int base = i * 2;
    if (base + 1 < n) {
        float2 a = *reinterpret_cast<const float2*>(g_accum + base);
        float2 c = *reinterpret_cast<const float2*>(special_cost + base);
        float2 r;
        float h;
        h = a.x - 1.0f; r.x = h * h * c.x;
        h = a.y - 1.0f; r.y = h * h * c.y;
        *reinterpret_cast<float2*>(out + base) = r;
        *reinterpret_cast<float2*>(g_accum + base) = make_float2(0.0f, 0.0f);
    } else if (base < n) {
        float h = g_accum[base] - 1.0f;
        out[base] = h * h * special_cost[base];
        g_accum[base] = 0.0f;
    }
}

// Fallback path (N > MAX_NODES): classic init/scatter/apply on d_out.
__global__ __launch_bounds__(256) void init_kernel(float* __restrict__ out, int n) {
    int i = blockIdx.x * blockDim.x + threadIdx.x;
    int base = i * 4;
    if (base + 3 < n) {
        *reinterpret_cast<float4*>(out + base) =
            make_float4(-1.0f, -1.0f, -1.0f, -1.0f);
    } else {
        for (int k = base; k < n; ++k) out[k] = -1.0f;
    }
}

__global__ __launch_bounds__(256) void scatter_out_kernel(
        const float* __restrict__ pred_prob,
        const int*   __restrict__ src,
        const int*   __restrict__ dst,
        float*       __restrict__ out,
        int num_edges) {
    int i = blockIdx.x * blockDim.x + threadIdx.x;
    int base = i * 2;
    if (base + 1 < num_edges) {
        int2 s2 = *reinterpret_cast<const int2*>(src + base);
        int2 d2 = *reinterpret_cast<const int2*>(dst + base);
        atomicAdd(out + d2.x, __ldg(pred_prob + s2.x));
        atomicAdd(out + d2.y, __ldg(pred_prob + s2.y));
    } else if (base < num_edges) {
        atomicAdd(out + dst[base], __ldg(pred_prob + src[base]));
    }
}

__global__ __launch_bounds__(256) void apply_inplace_kernel(
        float* __restrict__ out,
        const float* __restrict__ special_cost,
        int n) {
    int i = blockIdx.x * blockDim.x + threadIdx.x;
    int base = i * 4;
    if (base + 3 < n) {
        float4 h = *reinterpret_cast<const float4*>(out + base);
        float4 c = *reinterpret_cast<const float4*>(special_cost + base);
        h.x = h.x * h.x * c.x;
        h.y = h.y * h.y * c.y;
        h.z = h.z * h.z * c.z;
        h.w = h.w * h.w * c.w;
        *reinterpret_cast<float4*>(out + base) = h;
    } else {
        for (int k = base; k < n; ++k) {
            float h = out[k];
            out[k] = h * h * special_cost[k];
        }
    }
}

extern "C" void kernel_launch(void* const* d_in, const int* in_sizes, int n_in,
                              void* d_out, int out_size) {
    const float* pred_prob    = (const float*)d_in[0];
    const float* special_cost = (const float*)d_in[1];
    const int*   src          = (const int*)d_in[2];
    const int*   dst          = (const int*)d_in[3];
    float*       out          = (float*)d_out;

    const int N = in_sizes[0];
    const int E = in_sizes[2];

    const int threads = 256;
    int eblocks = ((E + 1) / 2 + threads - 1) / threads;

    if (N <= MAX_NODES) {
        int nblocks2 = ((N + 1) / 2 + threads - 1) / threads;
        scatter_accum_kernel<<<eblocks, threads>>>(pred_prob, src, dst, E);
        apply_reset_kernel<<<nblocks2, threads>>>(special_cost, out, N);
    } else {
        int nblocks = ((N + 3) / 4 + threads - 1) / threads;
        init_kernel<<<nblocks, threads>>>(out, N);
        scatter_out_kernel<<<eblocks, threads>>>(pred_prob, src, dst, out, E);
        apply_inplace_kernel<<<nblocks, threads>>>(out, special_cost, N);
    }
}

// round 12
// speedup vs baseline: 1.0136x; 1.0136x over previous
#include <cuda_runtime.h>
#include <cuda_bf16.h>
#include <cstdint>

// ---------------------------------------------------------------------------
// out[n] = (segment_sum(pred_prob[src], dst)[n] - 1)^2 * special_cost[n]
// N = 1,000,000 nodes, E = 16,000,000 edges.
//
// v12: 2-launch pipeline (scatter -> apply+reset) on zero-initialized
// __device__ scratch.
// Scatter (FROZEN at measured-best): 2 edges/thread, 256 threads, __ldg
// gather, atomicAdd -> RED. Floor ~122.5us (L1tex/LSU: 1 cyc/edge gather
// wavefront + 1.29 cyc/edge spread-RED per SM; batching axis fully swept).
// NEW: 128 prefetch blocks appended to the scatter grid (scheduled last ->
// run during the scatter's tail) warm special_cost into L2 via ld.global.cg
// -- scatter has ~7 TB/s of spare DRAM BW, and accum is already L2-hot from
// the REDs, so apply's only cold stream is special_cost.
// Apply: 2 elems/thread (measured best 6.14us; occ 80%).
// ---------------------------------------------------------------------------

#define MAX_NODES 1000000
#define PREFETCH_BLOCKS 128
__device__ float g_accum[MAX_NODES];   // static zero-init

__global__ __launch_bounds__(256) void scatter_accum_kernel(
        const float* __restrict__ pred_prob,
        const int*   __restrict__ src,
        const int*   __restrict__ dst,
        const float* __restrict__ special_cost,
        int num_edges,
        int edge_blocks,
        int num_nodes) {
    if ((int)blockIdx.x >= edge_blocks) {
        // Prefetch blocks: scheduled last, warm special_cost into L2 during
        // the scatter tail. Volatile .cg loads (L2 fill, no DCE).
        int pb  = blockIdx.x - edge_blocks;
        int tid = pb * blockDim.x + threadIdx.x;
        int stride = PREFETCH_BLOCKS * blockDim.x;
        int n4 = num_nodes >> 2;
        const float4* c4 = reinterpret_cast<const float4*>(special_cost);
        for (int k = tid; k < n4; k += stride) {
            float a, b, c, d;
            asm volatile("ld.global.cg.v4.f32 {%0,%1,%2,%3}, [%4];"
                         : "=f"(a), "=f"(b), "=f"(c), "=f"(d)
                         : "l"(c4 + k));
        }
        return;
    }
    int i = blockIdx.x * blockDim.x + threadIdx.x;
    int base = i * 2;
    if (base + 1 < num_edges) {
        int2 s2 = *reinterpret_cast<const int2*>(src + base);
        int2 d2 = *reinterpret_cast<const int2*>(dst + base);
        float m0 = __ldg(pred_prob + s2.x);
        float m1 = __ldg(pred_prob + s2.y);
        atomicAdd(g_accum + d2.x, m0);   // return unused -> RED
        atomicAdd(g_accum + d2.y, m1);
    } else if (base < num_edges) {
        atomicAdd(g_accum + dst[base], __ldg(pred_prob + src[base]));
    }
}

// Reads accumulated sums, computes (a-1)^2 * cost into out, and resets the
// accumulator to zero so the next (graph-replayed) call starts clean.
__global__ __launch_bounds__(256) void apply_reset_kernel(
        const float* __restrict__ special_cost,
        float*       __restrict__ out,
        int n) {
    int i = blockIdx.x * blockDim.x + threadIdx.x;
    int base = i * 2;
    if (base + 1 < n) {
        float2 a = *reinterpret_cast<const float2*>(g_accum + base);
        float2 c = *reinterpret_cast<const float2*>(special_cost + base);
        float2 r;
        float h;
        h = a.x - 1.0f; r.x = h * h * c.x;
        h = a.y - 1.0f; r.y = h * h * c.y;
        *reinterpret_cast<float2*>(out + base) = r;
        *reinterpret_cast<float2*>(g_accum + base) = make_float2(0.0f, 0.0f);
    } else if (base < n) {
        float h = g_accum[base] - 1.0f;
        out[base] = h * h * special_cost[base];
        g_accum[base] = 0.0f;
    }
}

// Fallback path (N > MAX_NODES): classic init/scatter/apply on d_out.
__global__ __launch_bounds__(256) void init_kernel(float* __restrict__ out, int n) {
    int i = blockIdx.x * blockDim.x + threadIdx.x;
    int base = i * 4;
    if (base + 3 < n) {
        *reinterpret_cast<float4*>(out + base) =
            make_float4(-1.0f, -1.0f, -1.0f, -1.0f);
    } else {
        for (int k = base; k < n; ++k) out[k] = -1.0f;
    }
}

__global__ __launch_bounds__(256) void scatter_out_kernel(
        const float* __restrict__ pred_prob,
        const int*   __restrict__ src,
        const int*   __restrict__ dst,
        float*       __restrict__ out,
        int num_edges) {
    int i = blockIdx.x * blockDim.x + threadIdx.x;
    int base = i * 2;
    if (base + 1 < num_edges) {
        int2 s2 = *reinterpret_cast<const int2*>(src + base);
        int2 d2 = *reinterpret_cast<const int2*>(dst + base);
        atomicAdd(out + d2.x, __ldg(pred_prob + s2.x));
        atomicAdd(out + d2.y, __ldg(pred_prob + s2.y));
    } else if (base < num_edges) {
        atomicAdd(out + dst[base], __ldg(pred_prob + src[base]));
    }
}

__global__ __launch_bounds__(256) void apply_inplace_kernel(
        float* __restrict__ out,
        const float* __restrict__ special_cost,
        int n) {
    int i = blockIdx.x * blockDim.x + threadIdx.x;
    int base = i * 4;
    if (base + 3 < n) {
        float4 h = *reinterpret_cast<const float4*>(out + base);
        float4 c = *reinterpret_cast<const float4*>(special_cost + base);
        h.x = h.x * h.x * c.x;
        h.y = h.y * h.y * c.y;
        h.z = h.z * h.z * c.z;
        h.w = h.w * h.w * c.w;
        *reinterpret_cast<float4*>(out + base) = h;
    } else {
        for (int k = base; k < n; ++k) {
            float h = out[k];
            out[k] = h * h * special_cost[k];
        }
    }
}

extern "C" void kernel_launch(void* const* d_in, const int* in_sizes, int n_in,
                              void* d_out, int out_size) {
    const float* pred_prob    = (const float*)d_in[0];
    const float* special_cost = (const float*)d_in[1];
    const int*   src          = (const int*)d_in[2];
    const int*   dst          = (const int*)d_in[3];
    float*       out          = (float*)d_out;

    const int N = in_sizes[0];
    const int E = in_sizes[2];

    const int threads = 256;
    int eblocks = ((E + 1) / 2 + threads - 1) / threads;

    if (N <= MAX_NODES) {
        int nblocks2 = ((N + 1) / 2 + threads - 1) / threads;
        scatter_accum_kernel<<<eblocks + PREFETCH_BLOCKS, threads>>>(
            pred_prob, src, dst, special_cost, E, eblocks, N);
        apply_reset_kernel<<<nblocks2, threads>>>(special_cost, out, N);
    } else {
        int nblocks = ((N + 3) / 4 + threads - 1) / threads;
        init_kernel<<<nblocks, threads>>>(out, N);
        scatter_out_kernel<<<eblocks, threads>>>(pred_prob, src, dst, out, E);
        apply_inplace_kernel<<<nblocks, threads>>>(out, special_cost, N);
    }
}